// round 13
// baseline (speedup 1.0000x reference)
#include <cuda_runtime.h>
#include <cuda_bf16.h>
#include <cstdint>

typedef unsigned long long u64;
typedef unsigned int u32;

// Problem constants
#define N_TOK     16384
#define N_E       8192
#define E_DIM     256
#define OUT_ELEMS 4194304
#define LOSS_OFF  OUT_ELEMS
#define PERP_OFF  (OUT_ELEMS + 1)
#define IDX_OFF   (OUT_ELEMS + 2)
#define MARGIN    8.0f
#define CAND_CAP  32

// Scratch (static device globals)
__device__ float          g_wT[E_DIM * N_E];      // weight transposed [k][n] (for gather)
__device__ float          g_wn[N_E];              // |w_n|^2
__device__ float          g_Azf[N_TOK * E_DIM];   // z transposed, fp32 [t][k]
__device__ __nv_bfloat16  g_Abf[N_TOK * E_DIM];   // z transposed, bf16 [t][k]
__device__ __nv_bfloat16  g_Bbf[N_E * E_DIM];     // w bf16 [n][k]
__device__ int            g_cand[N_TOK * CAND_CAP];
__device__ int            g_ccount[N_TOK];
__device__ int            g_ovf[N_TOK];
__device__ int            g_idx[N_TOK];
__device__ int            g_counts[N_E];
__device__ float          g_partial[256];

// ===========================================================================
// Helpers
// ===========================================================================
__device__ __forceinline__ u32 smem_to_u32(const void* p) {
    u32 a;
    asm("{ .reg .u64 t; cvta.to.shared.u64 t, %1; cvt.u32.u64 %0, t; }"
        : "=r"(a) : "l"(p));
    return a;
}
__device__ __forceinline__ void ldsm_x4(u32& r0, u32& r1, u32& r2, u32& r3, u32 addr) {
    asm volatile("ldmatrix.sync.aligned.m8n8.x4.shared.b16 {%0,%1,%2,%3}, [%4];"
                 : "=r"(r0), "=r"(r1), "=r"(r2), "=r"(r3) : "r"(addr));
}
__device__ __forceinline__ void mma_bf16(float* d, const u32* a, const u32* b) {
    asm volatile(
        "mma.sync.aligned.m16n8k16.row.col.f32.bf16.bf16.f32 "
        "{%0,%1,%2,%3}, {%4,%5,%6,%7}, {%8,%9}, {%0,%1,%2,%3};"
        : "+f"(d[0]), "+f"(d[1]), "+f"(d[2]), "+f"(d[3])
        : "r"(a[0]), "r"(a[1]), "r"(a[2]), "r"(a[3]), "r"(b[0]), "r"(b[1]));
}

// Swizzled smem address for a [128 rows][16 ksteps x 32B] tile stored as
// 16 x (128 rows x 32B) sub-tiles. Simultaneously: coalesced gmem load,
// conflict-free STS.128, conflict-free ldmatrix (distinct mod-128 quads).
__device__ __forceinline__ u32 sw_addr(u32 buf, int ks, int r, int h) {
    return buf + (u32)ks * 4096u + ((u32)(r ^ (ks & 3)) << 5)
           + ((u32)(h ^ ((r >> 2) & 1)) << 4);
}

// ===========================================================================
// Prep kernels
// ===========================================================================
__global__ void zero_kernel() {
    int i = blockIdx.x * 256 + threadIdx.x;
    if (i < N_E)   g_counts[i] = 0;
    if (i < N_TOK) g_ovf[i] = 0;
}

// weight [N_E, E_DIM] -> g_wT [E_DIM, N_E]  (for gather kernel)
__global__ void transpose_kernel(const float* __restrict__ w) {
    __shared__ float tile[32][33];
    int bx = blockIdx.x, by = blockIdx.y;
    int tx = threadIdx.x, ty = threadIdx.y;
#pragma unroll
    for (int j = 0; j < 32; j += 8)
        tile[ty + j][tx] = w[(by * 32 + ty + j) * E_DIM + bx * 32 + tx];
    __syncthreads();
#pragma unroll
    for (int j = 0; j < 32; j += 8)
        g_wT[(bx * 32 + ty + j) * N_E + by * 32 + tx] = tile[tx][ty + j];
}

__global__ void wn_kernel() {
    int j = blockIdx.x * 256 + threadIdx.x;
    float s = 0.f;
#pragma unroll 8
    for (int k = 0; k < E_DIM; k++) {
        float v = g_wT[k * N_E + j];
        s = fmaf(v, v, s);
    }
    g_wn[j] = s;
}

__global__ void wconv_kernel(const float* __restrict__ w) {
    int i = blockIdx.x * 256 + threadIdx.x;
    g_Bbf[i] = __float2bfloat16(w[i]);
}

// z [b, c, s] -> g_Azf/g_Abf [t][k]  with t = b*4096 + s, k = c
__global__ void zprep_kernel(const float* __restrict__ z) {
    __shared__ float tile[32][33];
    int k0 = blockIdx.x * 32, s0 = blockIdx.y * 32, b = blockIdx.z;
    int tx = threadIdx.x, ty = threadIdx.y;
#pragma unroll
    for (int j = 0; j < 32; j += 8)
        tile[ty + j][tx] = z[(size_t)b * 1048576 + (size_t)(k0 + ty + j) * 4096 + s0 + tx];
    __syncthreads();
#pragma unroll
    for (int j = 0; j < 32; j += 8) {
        int t = b * 4096 + s0 + ty + j;
        float v = tile[tx][ty + j];
        g_Azf[(size_t)t * 256 + k0 + tx] = v;
        g_Abf[(size_t)t * 256 + k0 + tx] = __float2bfloat16(v);
    }
}

// ===========================================================================
// Tensor-core (mma.sync bf16) approximate argmin + candidate collection.
// 128 CTAs x 256 threads. 8 warps, each owns 16 tokens x all 128 codes of
// the current N-tile. A fragments live in registers for the whole kernel.
// ===========================================================================
#define SMEM_BYTES (65536 + 2048 + 128)

__global__ __launch_bounds__(256, 1) void argmin_mma_kernel() {
    extern __shared__ char smem_raw[];
    const u32 sb  = smem_to_u32(smem_raw);
    const u32 BUF = (sb + 127u) & ~127u;
    char* bufp = smem_raw + (BUF - sb);
    float* wn_s   = (float*)(bufp + 65536);
    float* rmin_s = (float*)(bufp + 66048);
    int*   cnt_s  = (int*)(bufp + 66560);
    int*   ovf_s  = (int*)(bufp + 67072);

    const int tid = threadIdx.x, w = tid >> 5, lane = tid & 31;
    const int gr = lane >> 2, qc = lane & 3;
    const int t0 = blockIdx.x * 128;

    if (tid < 128) { rmin_s[tid] = 3.4e38f; cnt_s[tid] = 0; ovf_s[tid] = 0; }

    // ---- stage A tile (128 tok x 256 bf16) into buffer, swizzled
    {
        const uint4* Asrc = (const uint4*)(g_Abf + (size_t)t0 * E_DIM);
#pragma unroll
        for (int it = 0; it < 16; it++) {
            int idx = it * 256 + tid;
            int r = idx >> 5, kc = idx & 31;
            u32 d = sw_addr(BUF, kc >> 1, r, kc & 1);
            *(uint4*)(smem_raw + (d - sb)) = Asrc[idx];
        }
    }
    __syncthreads();

    // ---- ldmatrix A fragments into registers (16 ksteps x 4 regs)
    u32 afr[16][4];
    {
        int j  = lane >> 3;
        int rl = (lane & 7) + ((j & 1) << 3);
        int h  = j >> 1;
        int m  = w * 16 + rl;
#pragma unroll
        for (int ks = 0; ks < 16; ks++) {
            u32 a = sw_addr(BUF, ks, m, h);
            ldsm_x4(afr[ks][0], afr[ks][1], afr[ks][2], afr[ks][3], a);
        }
    }

    // B ldmatrix lane geometry
    const int bj  = lane >> 3;
    const int bnl = (lane & 7) + ((bj >> 1) << 3);
    const int bh  = bj & 1;

    const int r_lo = w * 16 + gr, r_hi = r_lo + 8;

    for (int nt = 0; nt < 64; nt++) {
        const int n0 = nt * 128;
        __syncthreads();   // previous tile's B + rmin fully consumed
        // ---- load B tile (128 codes x 256 bf16), coalesced + swizzled
        const uint4* Bsrc = (const uint4*)(g_Bbf + (size_t)n0 * E_DIM);
#pragma unroll
        for (int it = 0; it < 16; it++) {
            int idx = it * 256 + tid;
            int r = idx >> 5, kc = idx & 31;
            u32 d = sw_addr(BUF, kc >> 1, r, kc & 1);
            *(uint4*)(smem_raw + (d - sb)) = Bsrc[idx];
        }
        if (tid < 32)
            ((float4*)wn_s)[tid] = *(const float4*)&g_wn[n0 + tid * 4];
        __syncthreads();

        // ---- GEMM: 16 n-frags x 16 ksteps of m16n8k16
        float acc[16][4];
#pragma unroll
        for (int f = 0; f < 16; f++) {
            acc[f][0] = 0.f; acc[f][1] = 0.f; acc[f][2] = 0.f; acc[f][3] = 0.f;
        }
#pragma unroll
        for (int ks = 0; ks < 16; ks++) {
            u32 b[16][2];
#pragma unroll
            for (int q = 0; q < 8; q++) {
                int n = q * 16 + bnl;
                u32 a = sw_addr(BUF, ks, n, bh);
                ldsm_x4(b[2*q][0], b[2*q][1], b[2*q+1][0], b[2*q+1][1], a);
            }
#pragma unroll
            for (int f = 0; f < 16; f++) mma_bf16(acc[f], afr[ks], b[f]);
        }

        // ---- epilogue: score = wn - 2*dot, candidate collection
        float rm_lo = rmin_s[r_lo], rm_hi = rmin_s[r_hi];
        const float th_lo = rm_lo + MARGIN, th_hi = rm_hi + MARGIN;
        float nlo = rm_lo, nhi = rm_hi;
#pragma unroll
        for (int f = 0; f < 16; f++) {
            int c0 = f * 8 + qc * 2;
            float w0 = wn_s[c0], w1 = wn_s[c0 + 1];
            float s0 = fmaf(-2.f, acc[f][0], w0);
            float s1 = fmaf(-2.f, acc[f][1], w1);
            float s2 = fmaf(-2.f, acc[f][2], w0);
            float s3 = fmaf(-2.f, acc[f][3], w1);
            if (s0 < th_lo) {
                int sl = atomicAdd(&cnt_s[r_lo], 1);
                if (sl < CAND_CAP) g_cand[(size_t)(t0 + r_lo) * CAND_CAP + sl] = n0 + c0;
                else ovf_s[r_lo] = 1;
                if (s0 < nlo) nlo = s0;
            }
            if (s1 < th_lo) {
                int sl = atomicAdd(&cnt_s[r_lo], 1);
                if (sl < CAND_CAP) g_cand[(size_t)(t0 + r_lo) * CAND_CAP + sl] = n0 + c0 + 1;
                else ovf_s[r_lo] = 1;
                if (s1 < nlo) nlo = s1;
            }
            if (s2 < th_hi) {
                int sl = atomicAdd(&cnt_s[r_hi], 1);
                if (sl < CAND_CAP) g_cand[(size_t)(t0 + r_hi) * CAND_CAP + sl] = n0 + c0;
                else ovf_s[r_hi] = 1;
                if (s2 < nhi) nhi = s2;
            }
            if (s3 < th_hi) {
                int sl = atomicAdd(&cnt_s[r_hi], 1);
                if (sl < CAND_CAP) g_cand[(size_t)(t0 + r_hi) * CAND_CAP + sl] = n0 + c0 + 1;
                else ovf_s[r_hi] = 1;
                if (s3 < nhi) nhi = s3;
            }
        }
        // reduce running min over the 4 quad lanes of each row
#pragma unroll
        for (int o = 1; o <= 2; o <<= 1) {
            nlo = fminf(nlo, __shfl_xor_sync(0xffffffffu, nlo, o));
            nhi = fminf(nhi, __shfl_xor_sync(0xffffffffu, nhi, o));
        }
        if (qc == 0) { rmin_s[r_lo] = nlo; rmin_s[r_hi] = nhi; }
    }

    __syncthreads();
    if (qc == 0) {
        int c1 = cnt_s[r_lo];
        g_ccount[t0 + r_lo] = c1 < CAND_CAP ? c1 : CAND_CAP;
        if (ovf_s[r_lo]) g_ovf[t0 + r_lo] = 1;
        int c2 = cnt_s[r_hi];
        g_ccount[t0 + r_hi] = c2 < CAND_CAP ? c2 : CAND_CAP;
        if (ovf_s[r_hi]) g_ovf[t0 + r_hi] = 1;
    }
}

// ===========================================================================
// Exact fp32 rescore of candidates (warp per token). True argmin guaranteed
// in candidate set (margin >> 2x worst-case bf16 score error). Lowest-index
// tie-break matches jnp.argmin.
// ===========================================================================
__global__ __launch_bounds__(256) void rescore_kernel(const float* __restrict__ w) {
    const int wid = threadIdx.x >> 5, lane = threadIdx.x & 31;
    const int t = blockIdx.x * 8 + wid;

    const float4 za = *(const float4*)&g_Azf[(size_t)t * 256 + lane * 4];
    const float4 zb = *(const float4*)&g_Azf[(size_t)t * 256 + 128 + lane * 4];

    const int cnt = g_ccount[t];
    const int ovf = g_ovf[t];
    const int niter = ovf ? N_E : cnt;

    float best = 3.4e38f;
    int   bi = 0x7fffffff;
    for (int it = 0; it < niter; it++) {
        const int j = ovf ? it : g_cand[(size_t)t * CAND_CAP + it];
        const float4 wa = *(const float4*)&w[(size_t)j * 256 + lane * 4];
        const float4 wb = *(const float4*)&w[(size_t)j * 256 + 128 + lane * 4];
        float d = za.x * wa.x;
        d = fmaf(za.y, wa.y, d);
        d = fmaf(za.z, wa.z, d);
        d = fmaf(za.w, wa.w, d);
        d = fmaf(zb.x, wb.x, d);
        d = fmaf(zb.y, wb.y, d);
        d = fmaf(zb.z, wb.z, d);
        d = fmaf(zb.w, wb.w, d);
#pragma unroll
        for (int off = 16; off >= 1; off >>= 1)
            d += __shfl_xor_sync(0xffffffffu, d, off);
        float score = fmaf(-2.f, d, g_wn[j]);
        if (score < best || (score == best && j < bi)) { best = score; bi = j; }
    }
    if (lane == 0) {
        g_idx[t] = bi;
        atomicAdd(&g_counts[bi], 1);
    }
}

// ===========================================================================
// Gather + straight-through output + loss partials
// ===========================================================================
__global__ __launch_bounds__(256) void gather_kernel(const float* __restrict__ z,
                                                     float* __restrict__ out,
                                                     int out_size) {
    __shared__ float red[256];
    const int blk = blockIdx.x;
    const int t0 = blk * 64;
    const int b  = t0 >> 12;
    const int s0 = t0 & 4095;
    const int tid = threadIdx.x;
    const int i  = tid & 63;
    const int cg = tid >> 6;
    const int t  = t0 + i;
    const int j  = g_idx[t];
    const size_t bse = (size_t)b * 1048576 + s0 + i;

    float lsum = 0.f;
#pragma unroll 4
    for (int cc = 0; cc < 64; cc++) {
        int c = cg * 64 + cc;
        float zt = z[bse + (size_t)c * 4096];
        float zq = g_wT[(size_t)c * N_E + j];
        float d = zq - zt;
        out[bse + (size_t)c * 4096] = zt + d;
        lsum = fmaf(d, d, lsum);
    }

    red[tid] = lsum;
    __syncthreads();
    for (int s = 128; s >= 1; s >>= 1) {
        if (tid < s) red[tid] += red[tid + s];
        __syncthreads();
    }
    if (tid == 0) g_partial[blk] = red[0];

    if (cg == 0 && out_size >= IDX_OFF + N_TOK)
        out[IDX_OFF + t] = (float)j;
}

__global__ void final_kernel(float* __restrict__ out, int out_size) {
    __shared__ float red[256];
    const int tid = threadIdx.x;

    red[tid] = g_partial[tid];
    __syncthreads();
    for (int s = 128; s >= 1; s >>= 1) {
        if (tid < s) red[tid] += red[tid + s];
        __syncthreads();
    }
    float loss = 0.25f * red[0] / (float)OUT_ELEMS;
    __syncthreads();

    float h = 0.f;
#pragma unroll
    for (int k = 0; k < N_E / 256; k++) {
        float p = (float)g_counts[k * 256 + tid] * (1.f / (float)N_TOK);
        h += p * logf(p + 1e-10f);
    }
    red[tid] = h;
    __syncthreads();
    for (int s = 128; s >= 1; s >>= 1) {
        if (tid < s) red[tid] += red[tid + s];
        __syncthreads();
    }
    if (tid == 0) {
        if (out_size > LOSS_OFF) out[LOSS_OFF] = loss;
        if (out_size > PERP_OFF) out[PERP_OFF] = expf(-red[0]);
    }
}

// ===========================================================================
extern "C" void kernel_launch(void* const* d_in, const int* in_sizes, int n_in,
                              void* d_out, int out_size) {
    const float* z = (const float*)d_in[0];
    const float* w = (const float*)d_in[1];
    if (n_in >= 2 && in_sizes[0] == N_E * E_DIM && in_sizes[1] == OUT_ELEMS) {
        const float* tmp = z; z = w; w = tmp;
    }
    float* out = (float*)d_out;

    cudaFuncSetAttribute(argmin_mma_kernel,
                         cudaFuncAttributeMaxDynamicSharedMemorySize, SMEM_BYTES);

    zero_kernel<<<64, 256>>>();
    transpose_kernel<<<dim3(8, 256), dim3(32, 8)>>>(w);
    wn_kernel<<<N_E / 256, 256>>>();
    wconv_kernel<<<N_E * E_DIM / 256, 256>>>(w);
    zprep_kernel<<<dim3(8, 128, 4), dim3(32, 8)>>>(z);
    argmin_mma_kernel<<<N_TOK / 128, 256, SMEM_BYTES>>>();
    rescore_kernel<<<N_TOK / 8, 256>>>(w);
    gather_kernel<<<N_TOK / 64, 256>>>(z, out, out_size);
    final_kernel<<<1, 256>>>(out, out_size);
}

// round 14
// speedup vs baseline: 6.7249x; 6.7249x over previous
#include <cuda_runtime.h>

// Problem constants
#define N_TOK    16384          // 4 * 16*16*16 tokens
#define N_E      8192           // codebook size
#define E_DIM    256            // codebook dim
#define OUT_ELEMS 4194304       // 4*256*16*16*16
#define LOSS_OFF  OUT_ELEMS
#define PERP_OFF  (OUT_ELEMS + 1)
#define IDX_OFF   (OUT_ELEMS + 2)
#define N_HALF   2              // codebook split factor (grid.y)

// Scratch (static device globals — allowed by harness rules)
__device__ float g_wT[E_DIM * N_E];   // weight transposed: [k][n]
__device__ float g_wn[N_E];           // |w_n|^2
__device__ float g_bestv[N_HALF * N_TOK];
__device__ int   g_besti[N_HALF * N_TOK];
__device__ int   g_idx[N_TOK];
__device__ int   g_counts[N_E];
__device__ float g_partial[256];

typedef unsigned long long u64;

__device__ __forceinline__ u64 pk2(float lo, float hi) {
    u64 r;
    asm("mov.b64 %0, {%1, %2};" : "=l"(r) : "f"(lo), "f"(hi));
    return r;
}
__device__ __forceinline__ void upk2(u64 v, float& lo, float& hi) {
    asm("mov.b64 {%0, %1}, %2;" : "=f"(lo), "=f"(hi) : "l"(v));
}
// packed fp32x2 FMA: d = a*b + d (two exact fp32 FMAs per instruction)
__device__ __forceinline__ void fma2(u64& d, u64 a, u64 b) {
    asm("fma.rn.f32x2 %0, %1, %2, %0;" : "+l"(d) : "l"(a), "l"(b));
}

// ---------------------------------------------------------------------------
__global__ void zero_kernel() {
    int i = blockIdx.x * blockDim.x + threadIdx.x;
    if (i < N_E) g_counts[i] = 0;
}

// ---------------------------------------------------------------------------
// Transpose weight [N_E, E_DIM] -> g_wT [E_DIM, N_E]
__global__ void transpose_kernel(const float* __restrict__ w) {
    __shared__ float tile[32][33];
    int bx = blockIdx.x;            // k tile (0..7)
    int by = blockIdx.y;            // n tile (0..255)
    int tx = threadIdx.x;           // 0..31
    int ty = threadIdx.y;           // 0..7
#pragma unroll
    for (int j = 0; j < 32; j += 8)
        tile[ty + j][tx] = w[(by * 32 + ty + j) * E_DIM + bx * 32 + tx];
    __syncthreads();
#pragma unroll
    for (int j = 0; j < 32; j += 8)
        g_wT[(bx * 32 + ty + j) * N_E + by * 32 + tx] = tile[tx][ty + j];
}

// ---------------------------------------------------------------------------
// wn[j] = sum_k wT[k][j]^2  (coalesced along j)
__global__ void wn_kernel() {
    int j = blockIdx.x * 256 + threadIdx.x;
    float s = 0.f;
#pragma unroll 8
    for (int k = 0; k < E_DIM; k++) {
        float v = g_wT[k * N_E + j];
        s = fmaf(v, v, s);
    }
    g_wn[j] = s;
}

// ---------------------------------------------------------------------------
// Argmin kernel: tiled 128x128x32 fp32 GEMM with distance epilogue.
// score(t, n) = |w_n|^2 - 2 * z_t . w_n   (|z_t|^2 constant per token)
// grid = (N_TOK/128, N_HALF): blockIdx.y selects a 4096-code half of the
// codebook so 256 CTAs cover all 148 SMs with 2 CTAs/SM co-residency.
#define BM 128
#define BN 128
#define BK 32

__global__ __launch_bounds__(256, 2) void argmin_kernel(const float* __restrict__ z) {
    __shared__ float zs[BK][BM];
    __shared__ float ws[BK][BN];

    const int tid = threadIdx.x;
    const int tx = tid & 15;        // code group (16)
    const int ty = tid >> 4;        // token group (16)
    const int t0 = blockIdx.x * BM; // 128 tokens, all in same batch
    const int half = blockIdx.y;
    const int b  = t0 >> 12;
    const int s0 = t0 & 4095;
    const float* zbase = z + (size_t)b * 1048576 + s0;  // zf[t][c] = z[b, c, s]

    float best[8];
    int   bidx[8];
#pragma unroll
    for (int i = 0; i < 8; i++) { best[i] = 1e30f; bidx[i] = 0; }

    const int nt_beg = half * (N_E / N_HALF / BN);
    const int nt_end = nt_beg + (N_E / N_HALF / BN);
    for (int nt = nt_beg; nt < nt_end; nt++) {
        const int n0 = nt * BN;

        u64 acc[8][4];
#pragma unroll
        for (int i = 0; i < 8; i++)
#pragma unroll
            for (int p = 0; p < 4; p++) acc[i][p] = 0ull;

        for (int kt = 0; kt < E_DIM / BK; kt++) {
            const int k0 = kt * BK;
            // load z tile: zs[k][m] = z[b, k0+k, s0+m]  (coalesced float4)
#pragma unroll
            for (int it = 0; it < 4; it++) {
                int slot = it * 256 + tid;
                int k = slot >> 5;
                int m4 = (slot & 31) << 2;
                *(float4*)&zs[k][m4] =
                    *(const float4*)&zbase[(size_t)(k0 + k) * 4096 + m4];
            }
            // load w tile from transposed weights (coalesced float4)
#pragma unroll
            for (int it = 0; it < 4; it++) {
                int slot = it * 256 + tid;
                int k = slot >> 5;
                int n4 = (slot & 31) << 2;
                *(float4*)&ws[k][n4] =
                    *(const float4*)&g_wT[(size_t)(k0 + k) * N_E + n0 + n4];
            }
            __syncthreads();

#pragma unroll 8
            for (int k = 0; k < BK; k++) {
                float4 za = *(const float4*)&zs[k][ty * 8];
                float4 zb = *(const float4*)&zs[k][ty * 8 + 4];
                float4 wa = *(const float4*)&ws[k][tx * 8];
                float4 wb = *(const float4*)&ws[k][tx * 8 + 4];
                u64 wp[4];
                wp[0] = pk2(wa.x, wa.y);
                wp[1] = pk2(wa.z, wa.w);
                wp[2] = pk2(wb.x, wb.y);
                wp[3] = pk2(wb.z, wb.w);
                float zv[8] = {za.x, za.y, za.z, za.w, zb.x, zb.y, zb.z, zb.w};
#pragma unroll
                for (int i = 0; i < 8; i++) {
                    u64 zz = pk2(zv[i], zv[i]);
#pragma unroll
                    for (int p = 0; p < 4; p++) fma2(acc[i][p], zz, wp[p]);
                }
            }
            __syncthreads();
        }

        // epilogue: score = wn - 2*dot, keep running min (ties -> lowest n wins)
        float wn8[8];
#pragma unroll
        for (int j = 0; j < 8; j++) wn8[j] = g_wn[n0 + tx * 8 + j];
#pragma unroll
        for (int i = 0; i < 8; i++) {
#pragma unroll
            for (int p = 0; p < 4; p++) {
                float d0, d1;
                upk2(acc[i][p], d0, d1);
                float sc0 = fmaf(-2.f, d0, wn8[2 * p]);
                float sc1 = fmaf(-2.f, d1, wn8[2 * p + 1]);
                int nA = n0 + tx * 8 + 2 * p;
                if (sc0 < best[i]) { best[i] = sc0; bidx[i] = nA; }
                if (sc1 < best[i]) { best[i] = sc1; bidx[i] = nA + 1; }
            }
        }
    }

    // reduce across the 16 tx lanes (lanes [0..15] / [16..31] within each warp)
#pragma unroll
    for (int i = 0; i < 8; i++) {
        float v = best[i];
        int   bi = bidx[i];
#pragma unroll
        for (int off = 8; off >= 1; off >>= 1) {
            float ov = __shfl_xor_sync(0xffffffffu, v, off);
            int   oi = __shfl_xor_sync(0xffffffffu, bi, off);
            if (ov < v || (ov == v && oi < bi)) { v = ov; bi = oi; }
        }
        if (tx == 0) {
            int t = t0 + ty * 8 + i;
            g_bestv[half * N_TOK + t] = v;
            g_besti[half * N_TOK + t] = bi;
        }
    }
}

// ---------------------------------------------------------------------------
// Merge the per-half winners: smaller score wins; tie -> lower index
// (half 0 always has lower indices, so tie -> half 0). Histogram counts.
__global__ void merge_kernel() {
    int t = blockIdx.x * 256 + threadIdx.x;
    float v0 = g_bestv[t],        v1 = g_bestv[N_TOK + t];
    int   i0 = g_besti[t],        i1 = g_besti[N_TOK + t];
    int bi = (v1 < v0) ? i1 : i0;
    g_idx[t] = bi;
    atomicAdd(&g_counts[bi], 1);
}

// ---------------------------------------------------------------------------
// Gather + straight-through output + deterministic loss partials.
__global__ __launch_bounds__(256) void gather_kernel(const float* __restrict__ z,
                                                     float* __restrict__ out,
                                                     int out_size) {
    __shared__ float red[256];
    const int blk = blockIdx.x;
    const int t0 = blk * 64;            // 64 tokens per block (same batch)
    const int b  = t0 >> 12;
    const int s0 = t0 & 4095;
    const int tid = threadIdx.x;
    const int i  = tid & 63;            // token within group
    const int cg = tid >> 6;            // channel group (0..3)
    const int t  = t0 + i;
    const int j  = g_idx[t];
    const size_t base = (size_t)b * 1048576 + s0 + i;

    float lsum = 0.f;
#pragma unroll 4
    for (int cc = 0; cc < 64; cc++) {
        int c = cg * 64 + cc;
        float zt = z[base + (size_t)c * 4096];
        float zq = g_wT[(size_t)c * N_E + j];
        float d = zq - zt;
        out[base + (size_t)c * 4096] = zt + d;   // straight-through value
        lsum = fmaf(d, d, lsum);
    }

    red[tid] = lsum;
    __syncthreads();
    for (int s = 128; s >= 1; s >>= 1) {
        if (tid < s) red[tid] += red[tid + s];
        __syncthreads();
    }
    if (tid == 0) g_partial[blk] = red[0];

    if (cg == 0 && out_size >= IDX_OFF + N_TOK)
        out[IDX_OFF + t] = (float)j;
}

// ---------------------------------------------------------------------------
// Final: loss + perplexity (deterministic fixed-order reductions)
__global__ void final_kernel(float* __restrict__ out, int out_size) {
    __shared__ float red[256];
    const int tid = threadIdx.x;

    red[tid] = g_partial[tid];
    __syncthreads();
    for (int s = 128; s >= 1; s >>= 1) {
        if (tid < s) red[tid] += red[tid + s];
        __syncthreads();
    }
    float loss = 0.25f * red[0] / (float)OUT_ELEMS;
    __syncthreads();

    float h = 0.f;
#pragma unroll
    for (int k = 0; k < N_E / 256; k++) {
        float p = (float)g_counts[k * 256 + tid] * (1.f / (float)N_TOK);
        h += p * logf(p + 1e-10f);
    }
    red[tid] = h;
    __syncthreads();
    for (int s = 128; s >= 1; s >>= 1) {
        if (tid < s) red[tid] += red[tid + s];
        __syncthreads();
    }
    if (tid == 0) {
        if (out_size > LOSS_OFF) out[LOSS_OFF] = loss;
        if (out_size > PERP_OFF) out[PERP_OFF] = expf(-red[0]);
    }
}

// ---------------------------------------------------------------------------
extern "C" void kernel_launch(void* const* d_in, const int* in_sizes, int n_in,
                              void* d_out, int out_size) {
    const float* z = (const float*)d_in[0];
    const float* w = (const float*)d_in[1];
    // defensive: inputs are (z: 4194304, weight: 2097152) — swap if reversed
    if (n_in >= 2 && in_sizes[0] == N_E * E_DIM && in_sizes[1] == OUT_ELEMS) {
        const float* tmp = z; z = w; w = tmp;
    }
    float* out = (float*)d_out;

    zero_kernel<<<32, 256>>>();
    transpose_kernel<<<dim3(8, 256), dim3(32, 8)>>>(w);
    wn_kernel<<<N_E / 256, 256>>>();
    argmin_kernel<<<dim3(N_TOK / BM, N_HALF), 256>>>(z);
    merge_kernel<<<N_TOK / 256, 256>>>();
    gather_kernel<<<N_TOK / 64, 256>>>(z, out, out_size);
    final_kernel<<<1, 256>>>(out, out_size);
}

// round 15
// speedup vs baseline: 7.2934x; 1.0845x over previous
#include <cuda_runtime.h>

// Problem constants
#define N_TOK    16384          // 4 * 16*16*16 tokens
#define N_E      8192           // codebook size
#define E_DIM    256            // codebook dim
#define OUT_ELEMS 4194304       // 4*256*16*16*16
#define LOSS_OFF  OUT_ELEMS
#define PERP_OFF  (OUT_ELEMS + 1)
#define IDX_OFF   (OUT_ELEMS + 2)
#define N_HALF   2              // codebook split factor (grid.y)

// Scratch (static device globals — allowed by harness rules)
__device__ float g_wT[E_DIM * N_E];   // weight transposed: [k][n]
__device__ float g_wn[N_E];           // |w_n|^2
__device__ float g_bestv[N_HALF * N_TOK];
__device__ int   g_besti[N_HALF * N_TOK];
__device__ int   g_idx[N_TOK];
__device__ int   g_counts[N_E];
__device__ float g_partial[256];

typedef unsigned long long u64;
typedef unsigned int u32;

__device__ __forceinline__ u64 pk2(float lo, float hi) {
    u64 r;
    asm("mov.b64 %0, {%1, %2};" : "=l"(r) : "f"(lo), "f"(hi));
    return r;
}
__device__ __forceinline__ void upk2(u64 v, float& lo, float& hi) {
    asm("mov.b64 {%0, %1}, %2;" : "=f"(lo), "=f"(hi) : "l"(v));
}
// packed fp32x2 FMA: d = a*b + d (two exact fp32 FMAs per instruction)
__device__ __forceinline__ void fma2(u64& d, u64 a, u64 b) {
    asm("fma.rn.f32x2 %0, %1, %2, %0;" : "+l"(d) : "l"(a), "l"(b));
}
__device__ __forceinline__ u32 smem_u32(const void* p) {
    u32 a;
    asm("{ .reg .u64 t; cvta.to.shared.u64 t, %1; cvt.u32.u64 %0, t; }"
        : "=r"(a) : "l"(p));
    return a;
}
__device__ __forceinline__ void cp16(u32 dst, const float* src) {
    asm volatile("cp.async.cg.shared.global [%0], [%1], 16;"
                 :: "r"(dst), "l"(src));
}

// ---------------------------------------------------------------------------
__global__ void zero_kernel() {
    int i = blockIdx.x * blockDim.x + threadIdx.x;
    if (i < N_E) g_counts[i] = 0;
}

// ---------------------------------------------------------------------------
// Transpose weight [N_E, E_DIM] -> g_wT [E_DIM, N_E]
__global__ void transpose_kernel(const float* __restrict__ w) {
    __shared__ float tile[32][33];
    int bx = blockIdx.x, by = blockIdx.y;
    int tx = threadIdx.x, ty = threadIdx.y;
#pragma unroll
    for (int j = 0; j < 32; j += 8)
        tile[ty + j][tx] = w[(by * 32 + ty + j) * E_DIM + bx * 32 + tx];
    __syncthreads();
#pragma unroll
    for (int j = 0; j < 32; j += 8)
        g_wT[(bx * 32 + ty + j) * N_E + by * 32 + tx] = tile[tx][ty + j];
}

// ---------------------------------------------------------------------------
__global__ void wn_kernel() {
    int j = blockIdx.x * 256 + threadIdx.x;
    float s = 0.f;
#pragma unroll 8
    for (int k = 0; k < E_DIM; k++) {
        float v = g_wT[k * N_E + j];
        s = fmaf(v, v, s);
    }
    g_wn[j] = s;
}

// ---------------------------------------------------------------------------
// Argmin kernel: tiled 128x128x32 fp32 GEMM with distance epilogue,
// cp.async double-buffered tile pipeline.
// score(t, n) = |w_n|^2 - 2 * z_t . w_n
#define BM 128
#define BN 128
#define BK 32
#define TILE_Z (BK * BM)     // floats per z tile
#define TILE_W (BK * BN)     // floats per w tile
#define SMEM_BYTES (2 * (TILE_Z + TILE_W) * 4)   // 64 KB

__global__ __launch_bounds__(256, 2) void argmin_kernel(const float* __restrict__ z) {
    extern __shared__ float smem[];
    float* zs = smem;                    // [2][BK][BM]
    float* ws = smem + 2 * TILE_Z;       // [2][BK][BN]

    const int tid = threadIdx.x;
    const int tx = tid & 15;
    const int ty = tid >> 4;
    const int t0 = blockIdx.x * BM;
    const int half = blockIdx.y;
    const int b  = t0 >> 12;
    const int s0 = t0 & 4095;
    const float* zbase = z + (size_t)b * 1048576 + s0;

    // per-thread cp.async source/dest geometry (fixed across tiles)
    const int zk = tid >> 5;             // 0..7   (k row, +8 per it)
    const int zm4 = (tid & 31) << 2;     // 0..124 (m offset)
    const u32 zs_s = smem_u32(zs);
    const u32 ws_s = smem_u32(ws);

    float best[8];
    int   bidx[8];
#pragma unroll
    for (int i = 0; i < 8; i++) { best[i] = 1e30f; bidx[i] = 0; }

    u64 acc[8][4];
#pragma unroll
    for (int i = 0; i < 8; i++)
#pragma unroll
        for (int p = 0; p < 4; p++) acc[i][p] = 0ull;

    const int nt_beg = half * (N_E / N_HALF / BN);
    const int NT = N_E / N_HALF / BN;    // 32 n-tiles per CTA
    const int S = NT * (E_DIM / BK);     // 256 (nt,kt) tiles

    // ---- stage tile s into buffer s&1
    auto stage = [&](int s) {
        const int kt = s & 7, nt = nt_beg + (s >> 3);
        const int k0 = kt * BK, n0 = nt * BN;
        const int buf = s & 1;
        const u32 zdst = zs_s + (u32)(buf * TILE_Z * 4);
        const u32 wdst = ws_s + (u32)(buf * TILE_W * 4);
#pragma unroll
        for (int it = 0; it < 4; it++) {
            int k = zk + it * 8;
            cp16(zdst + (u32)((k * BM + zm4) * 4),
                 zbase + (size_t)(k0 + k) * 4096 + zm4);
        }
#pragma unroll
        for (int it = 0; it < 4; it++) {
            int k = zk + it * 8;
            cp16(wdst + (u32)((k * BN + zm4) * 4),
                 &g_wT[(size_t)(k0 + k) * N_E + n0 + zm4]);
        }
        asm volatile("cp.async.commit_group;" ::: "memory");
    };

    stage(0);

    for (int s = 0; s < S; s++) {
        const int buf = s & 1;
        const int kt = s & 7;
        const int n0 = (nt_beg + (s >> 3)) * BN;

        if (s + 1 < S) {
            stage(s + 1);
            asm volatile("cp.async.wait_group 1;" ::: "memory");
        } else {
            asm volatile("cp.async.wait_group 0;" ::: "memory");
        }
        __syncthreads();

        const float* zsb = zs + buf * TILE_Z;
        const float* wsb = ws + buf * TILE_W;
#pragma unroll 8
        for (int k = 0; k < BK; k++) {
            float4 za = *(const float4*)&zsb[k * BM + ty * 8];
            float4 zb = *(const float4*)&zsb[k * BM + ty * 8 + 4];
            float4 wa = *(const float4*)&wsb[k * BN + tx * 8];
            float4 wb = *(const float4*)&wsb[k * BN + tx * 8 + 4];
            u64 wp[4];
            wp[0] = pk2(wa.x, wa.y);
            wp[1] = pk2(wa.z, wa.w);
            wp[2] = pk2(wb.x, wb.y);
            wp[3] = pk2(wb.z, wb.w);
            float zv[8] = {za.x, za.y, za.z, za.w, zb.x, zb.y, zb.z, zb.w};
#pragma unroll
            for (int i = 0; i < 8; i++) {
                u64 zz = pk2(zv[i], zv[i]);
#pragma unroll
                for (int p = 0; p < 4; p++) fma2(acc[i][p], zz, wp[p]);
            }
        }
        __syncthreads();

        if (kt == 7) {
            // epilogue: score = wn - 2*dot, running min (ties -> lowest n)
            float wn8[8];
#pragma unroll
            for (int j = 0; j < 8; j++) wn8[j] = g_wn[n0 + tx * 8 + j];
#pragma unroll
            for (int i = 0; i < 8; i++) {
#pragma unroll
                for (int p = 0; p < 4; p++) {
                    float d0, d1;
                    upk2(acc[i][p], d0, d1);
                    float sc0 = fmaf(-2.f, d0, wn8[2 * p]);
                    float sc1 = fmaf(-2.f, d1, wn8[2 * p + 1]);
                    int nA = n0 + tx * 8 + 2 * p;
                    if (sc0 < best[i]) { best[i] = sc0; bidx[i] = nA; }
                    if (sc1 < best[i]) { best[i] = sc1; bidx[i] = nA + 1; }
                    acc[i][p] = 0ull;
                }
            }
        }
    }

    // reduce across the 16 tx lanes
#pragma unroll
    for (int i = 0; i < 8; i++) {
        float v = best[i];
        int   bi = bidx[i];
#pragma unroll
        for (int off = 8; off >= 1; off >>= 1) {
            float ov = __shfl_xor_sync(0xffffffffu, v, off);
            int   oi = __shfl_xor_sync(0xffffffffu, bi, off);
            if (ov < v || (ov == v && oi < bi)) { v = ov; bi = oi; }
        }
        if (tx == 0) {
            int t = t0 + ty * 8 + i;
            g_bestv[half * N_TOK + t] = v;
            g_besti[half * N_TOK + t] = bi;
        }
    }
}

// ---------------------------------------------------------------------------
// Merge the per-half winners: smaller score wins; tie -> half 0 (lower index).
__global__ void merge_kernel() {
    int t = blockIdx.x * 256 + threadIdx.x;
    float v0 = g_bestv[t],        v1 = g_bestv[N_TOK + t];
    int   i0 = g_besti[t],        i1 = g_besti[N_TOK + t];
    int bi = (v1 < v0) ? i1 : i0;
    g_idx[t] = bi;
    atomicAdd(&g_counts[bi], 1);
}

// ---------------------------------------------------------------------------
// Gather + straight-through output + deterministic loss partials.
__global__ __launch_bounds__(256) void gather_kernel(const float* __restrict__ z,
                                                     float* __restrict__ out,
                                                     int out_size) {
    __shared__ float red[256];
    const int blk = blockIdx.x;
    const int t0 = blk * 64;
    const int b  = t0 >> 12;
    const int s0 = t0 & 4095;
    const int tid = threadIdx.x;
    const int i  = tid & 63;
    const int cg = tid >> 6;
    const int t  = t0 + i;
    const int j  = g_idx[t];
    const size_t base = (size_t)b * 1048576 + s0 + i;

    float lsum = 0.f;
#pragma unroll 4
    for (int cc = 0; cc < 64; cc++) {
        int c = cg * 64 + cc;
        float zt = z[base + (size_t)c * 4096];
        float zq = g_wT[(size_t)c * N_E + j];
        float d = zq - zt;
        out[base + (size_t)c * 4096] = zt + d;
        lsum = fmaf(d, d, lsum);
    }

    red[tid] = lsum;
    __syncthreads();
    for (int s = 128; s >= 1; s >>= 1) {
        if (tid < s) red[tid] += red[tid + s];
        __syncthreads();
    }
    if (tid == 0) g_partial[blk] = red[0];

    if (cg == 0 && out_size >= IDX_OFF + N_TOK)
        out[IDX_OFF + t] = (float)j;
}

// ---------------------------------------------------------------------------
__global__ void final_kernel(float* __restrict__ out, int out_size) {
    __shared__ float red[256];
    const int tid = threadIdx.x;

    red[tid] = g_partial[tid];
    __syncthreads();
    for (int s = 128; s >= 1; s >>= 1) {
        if (tid < s) red[tid] += red[tid + s];
        __syncthreads();
    }
    float loss = 0.25f * red[0] / (float)OUT_ELEMS;
    __syncthreads();

    float h = 0.f;
#pragma unroll
    for (int k = 0; k < N_E / 256; k++) {
        float p = (float)g_counts[k * 256 + tid] * (1.f / (float)N_TOK);
        h += p * logf(p + 1e-10f);
    }
    red[tid] = h;
    __syncthreads();
    for (int s = 128; s >= 1; s >>= 1) {
        if (tid < s) red[tid] += red[tid + s];
        __syncthreads();
    }
    if (tid == 0) {
        if (out_size > LOSS_OFF) out[LOSS_OFF] = loss;
        if (out_size > PERP_OFF) out[PERP_OFF] = expf(-red[0]);
    }
}

// ---------------------------------------------------------------------------
extern "C" void kernel_launch(void* const* d_in, const int* in_sizes, int n_in,
                              void* d_out, int out_size) {
    const float* z = (const float*)d_in[0];
    const float* w = (const float*)d_in[1];
    if (n_in >= 2 && in_sizes[0] == N_E * E_DIM && in_sizes[1] == OUT_ELEMS) {
        const float* tmp = z; z = w; w = tmp;
    }
    float* out = (float*)d_out;

    cudaFuncSetAttribute(argmin_kernel,
                         cudaFuncAttributeMaxDynamicSharedMemorySize, SMEM_BYTES);

    zero_kernel<<<32, 256>>>();
    transpose_kernel<<<dim3(8, 256), dim3(32, 8)>>>(w);
    wn_kernel<<<N_E / 256, 256>>>();
    argmin_kernel<<<dim3(N_TOK / BM, N_HALF), 256, SMEM_BYTES>>>(z);
    merge_kernel<<<N_TOK / 256, 256>>>();
    gather_kernel<<<N_TOK / 64, 256>>>(z, out, out_size);
    final_kernel<<<1, 256>>>(out, out_size);
}

// round 16
// speedup vs baseline: 7.3054x; 1.0016x over previous
#include <cuda_runtime.h>

// Problem constants
#define N_TOK    16384          // 4 * 16*16*16 tokens
#define N_E      8192           // codebook size
#define E_DIM    256            // codebook dim
#define OUT_ELEMS 4194304       // 4*256*16*16*16
#define LOSS_OFF  OUT_ELEMS
#define PERP_OFF  (OUT_ELEMS + 1)
#define IDX_OFF   (OUT_ELEMS + 2)
#define N_HALF   2              // codebook split factor (grid.y)

// Scratch (static device globals — allowed by harness rules)
__device__ float g_wT[E_DIM * N_E];   // weight transposed: [k][n]
__device__ float g_wn[N_E];           // |w_n|^2
__device__ float g_bestv[N_HALF * N_TOK];
__device__ int   g_besti[N_HALF * N_TOK];
__device__ int   g_idx[N_TOK];
__device__ int   g_counts[N_E];
__device__ float g_partial[256];

typedef unsigned long long u64;
typedef unsigned int u32;

__device__ __forceinline__ u64 pk2(float lo, float hi) {
    u64 r;
    asm("mov.b64 %0, {%1, %2};" : "=l"(r) : "f"(lo), "f"(hi));
    return r;
}
__device__ __forceinline__ void upk2(u64 v, float& lo, float& hi) {
    asm("mov.b64 {%0, %1}, %2;" : "=f"(lo), "=f"(hi) : "l"(v));
}
// packed fp32x2 FMA: d = a*b + d (two exact fp32 FMAs per instruction)
__device__ __forceinline__ void fma2(u64& d, u64 a, u64 b) {
    asm("fma.rn.f32x2 %0, %1, %2, %0;" : "+l"(d) : "l"(a), "l"(b));
}
__device__ __forceinline__ u32 smem_u32(const void* p) {
    u32 a;
    asm("{ .reg .u64 t; cvta.to.shared.u64 t, %1; cvt.u32.u64 %0, t; }"
        : "=r"(a) : "l"(p));
    return a;
}
__device__ __forceinline__ void cp16(u32 dst, const float* src) {
    asm volatile("cp.async.cg.shared.global [%0], [%1], 16;"
                 :: "r"(dst), "l"(src));
}

// ---------------------------------------------------------------------------
__global__ void zero_kernel() {
    int i = blockIdx.x * blockDim.x + threadIdx.x;
    if (i < N_E) g_counts[i] = 0;
}

// ---------------------------------------------------------------------------
// Transpose weight [N_E, E_DIM] -> g_wT [E_DIM, N_E]
__global__ void transpose_kernel(const float* __restrict__ w) {
    __shared__ float tile[32][33];
    int bx = blockIdx.x, by = blockIdx.y;
    int tx = threadIdx.x, ty = threadIdx.y;
#pragma unroll
    for (int j = 0; j < 32; j += 8)
        tile[ty + j][tx] = w[(by * 32 + ty + j) * E_DIM + bx * 32 + tx];
    __syncthreads();
#pragma unroll
    for (int j = 0; j < 32; j += 8)
        g_wT[(bx * 32 + ty + j) * N_E + by * 32 + tx] = tile[tx][ty + j];
}

// ---------------------------------------------------------------------------
__global__ void wn_kernel() {
    int j = blockIdx.x * 256 + threadIdx.x;
    float s = 0.f;
#pragma unroll 8
    for (int k = 0; k < E_DIM; k++) {
        float v = g_wT[k * N_E + j];
        s = fmaf(v, v, s);
    }
    g_wn[j] = s;
}

// ---------------------------------------------------------------------------
// Argmin kernel: tiled 128x128x32 fp32 GEMM with distance epilogue,
// cp.async double-buffered tile pipeline.
// score(t, n) = |w_n|^2 - 2 * z_t . w_n
#define BM 128
#define BN 128
#define BK 32
#define TILE_Z (BK * BM)     // floats per z tile
#define TILE_W (BK * BN)     // floats per w tile
#define SMEM_BYTES (2 * (TILE_Z + TILE_W) * 4)   // 64 KB

__global__ __launch_bounds__(256, 2) void argmin_kernel(const float* __restrict__ z) {
    extern __shared__ float smem[];
    float* zs = smem;                    // [2][BK][BM]
    float* ws = smem + 2 * TILE_Z;       // [2][BK][BN]

    const int tid = threadIdx.x;
    const int tx = tid & 15;
    const int ty = tid >> 4;
    const int t0 = blockIdx.x * BM;
    const int half = blockIdx.y;
    const int b  = t0 >> 12;
    const int s0 = t0 & 4095;
    const float* zbase = z + (size_t)b * 1048576 + s0;

    // per-thread cp.async source/dest geometry (fixed across tiles)
    const int zk = tid >> 5;             // 0..7   (k row, +8 per it)
    const int zm4 = (tid & 31) << 2;     // 0..124 (m offset)
    const u32 zs_s = smem_u32(zs);
    const u32 ws_s = smem_u32(ws);

    float best[8];
    int   bidx[8];
#pragma unroll
    for (int i = 0; i < 8; i++) { best[i] = 1e30f; bidx[i] = 0; }

    u64 acc[8][4];
#pragma unroll
    for (int i = 0; i < 8; i++)
#pragma unroll
        for (int p = 0; p < 4; p++) acc[i][p] = 0ull;

    const int nt_beg = half * (N_E / N_HALF / BN);
    const int NT = N_E / N_HALF / BN;    // 32 n-tiles per CTA
    const int S = NT * (E_DIM / BK);     // 256 (nt,kt) tiles

    // ---- stage tile s into buffer s&1
    auto stage = [&](int s) {
        const int kt = s & 7, nt = nt_beg + (s >> 3);
        const int k0 = kt * BK, n0 = nt * BN;
        const int buf = s & 1;
        const u32 zdst = zs_s + (u32)(buf * TILE_Z * 4);
        const u32 wdst = ws_s + (u32)(buf * TILE_W * 4);
#pragma unroll
        for (int it = 0; it < 4; it++) {
            int k = zk + it * 8;
            cp16(zdst + (u32)((k * BM + zm4) * 4),
                 zbase + (size_t)(k0 + k) * 4096 + zm4);
        }
#pragma unroll
        for (int it = 0; it < 4; it++) {
            int k = zk + it * 8;
            cp16(wdst + (u32)((k * BN + zm4) * 4),
                 &g_wT[(size_t)(k0 + k) * N_E + n0 + zm4]);
        }
        asm volatile("cp.async.commit_group;" ::: "memory");
    };

    stage(0);

    for (int s = 0; s < S; s++) {
        const int buf = s & 1;
        const int kt = s & 7;
        const int n0 = (nt_beg + (s >> 3)) * BN;

        if (s + 1 < S) {
            stage(s + 1);
            asm volatile("cp.async.wait_group 1;" ::: "memory");
        } else {
            asm volatile("cp.async.wait_group 0;" ::: "memory");
        }
        __syncthreads();

        const float* zsb = zs + buf * TILE_Z;
        const float* wsb = ws + buf * TILE_W;
#pragma unroll 8
        for (int k = 0; k < BK; k++) {
            float4 za = *(const float4*)&zsb[k * BM + ty * 8];
            float4 zb = *(const float4*)&zsb[k * BM + ty * 8 + 4];
            float4 wa = *(const float4*)&wsb[k * BN + tx * 8];
            float4 wb = *(const float4*)&wsb[k * BN + tx * 8 + 4];
            u64 wp[4];
            wp[0] = pk2(wa.x, wa.y);
            wp[1] = pk2(wa.z, wa.w);
            wp[2] = pk2(wb.x, wb.y);
            wp[3] = pk2(wb.z, wb.w);
            float zv[8] = {za.x, za.y, za.z, za.w, zb.x, zb.y, zb.z, zb.w};
#pragma unroll
            for (int i = 0; i < 8; i++) {
                u64 zz = pk2(zv[i], zv[i]);
#pragma unroll
                for (int p = 0; p < 4; p++) fma2(acc[i][p], zz, wp[p]);
            }
        }
        __syncthreads();

        if (kt == 7) {
            // epilogue: score = wn - 2*dot, running min (ties -> lowest n)
            float wn8[8];
#pragma unroll
            for (int j = 0; j < 8; j++) wn8[j] = g_wn[n0 + tx * 8 + j];
#pragma unroll
            for (int i = 0; i < 8; i++) {
#pragma unroll
                for (int p = 0; p < 4; p++) {
                    float d0, d1;
                    upk2(acc[i][p], d0, d1);
                    float sc0 = fmaf(-2.f, d0, wn8[2 * p]);
                    float sc1 = fmaf(-2.f, d1, wn8[2 * p + 1]);
                    int nA = n0 + tx * 8 + 2 * p;
                    if (sc0 < best[i]) { best[i] = sc0; bidx[i] = nA; }
                    if (sc1 < best[i]) { best[i] = sc1; bidx[i] = nA + 1; }
                    acc[i][p] = 0ull;
                }
            }
        }
    }

    // reduce across the 16 tx lanes
#pragma unroll
    for (int i = 0; i < 8; i++) {
        float v = best[i];
        int   bi = bidx[i];
#pragma unroll
        for (int off = 8; off >= 1; off >>= 1) {
            float ov = __shfl_xor_sync(0xffffffffu, v, off);
            int   oi = __shfl_xor_sync(0xffffffffu, bi, off);
            if (ov < v || (ov == v && oi < bi)) { v = ov; bi = oi; }
        }
        if (tx == 0) {
            int t = t0 + ty * 8 + i;
            g_bestv[half * N_TOK + t] = v;
            g_besti[half * N_TOK + t] = bi;
        }
    }
}

// ---------------------------------------------------------------------------
// Merge the per-half winners: smaller score wins; tie -> half 0 (lower index).
__global__ void merge_kernel() {
    int t = blockIdx.x * 256 + threadIdx.x;
    float v0 = g_bestv[t],        v1 = g_bestv[N_TOK + t];
    int   i0 = g_besti[t],        i1 = g_besti[N_TOK + t];
    int bi = (v1 < v0) ? i1 : i0;
    g_idx[t] = bi;
    atomicAdd(&g_counts[bi], 1);
}

// ---------------------------------------------------------------------------
// Gather + straight-through output + deterministic loss partials.
__global__ __launch_bounds__(256) void gather_kernel(const float* __restrict__ z,
                                                     float* __restrict__ out,
                                                     int out_size) {
    __shared__ float red[256];
    const int blk = blockIdx.x;
    const int t0 = blk * 64;
    const int b  = t0 >> 12;
    const int s0 = t0 & 4095;
    const int tid = threadIdx.x;
    const int i  = tid & 63;
    const int cg = tid >> 6;
    const int t  = t0 + i;
    const int j  = g_idx[t];
    const size_t base = (size_t)b * 1048576 + s0 + i;

    float lsum = 0.f;
#pragma unroll 4
    for (int cc = 0; cc < 64; cc++) {
        int c = cg * 64 + cc;
        float zt = z[base + (size_t)c * 4096];
        float zq = g_wT[(size_t)c * N_E + j];
        float d = zq - zt;
        out[base + (size_t)c * 4096] = zt + d;
        lsum = fmaf(d, d, lsum);
    }

    red[tid] = lsum;
    __syncthreads();
    for (int s = 128; s >= 1; s >>= 1) {
        if (tid < s) red[tid] += red[tid + s];
        __syncthreads();
    }
    if (tid == 0) g_partial[blk] = red[0];

    if (cg == 0 && out_size >= IDX_OFF + N_TOK)
        out[IDX_OFF + t] = (float)j;
}

// ---------------------------------------------------------------------------
__global__ void final_kernel(float* __restrict__ out, int out_size) {
    __shared__ float red[256];
    const int tid = threadIdx.x;

    red[tid] = g_partial[tid];
    __syncthreads();
    for (int s = 128; s >= 1; s >>= 1) {
        if (tid < s) red[tid] += red[tid + s];
        __syncthreads();
    }
    float loss = 0.25f * red[0] / (float)OUT_ELEMS;
    __syncthreads();

    float h = 0.f;
#pragma unroll
    for (int k = 0; k < N_E / 256; k++) {
        float p = (float)g_counts[k * 256 + tid] * (1.f / (float)N_TOK);
        h += p * logf(p + 1e-10f);
    }
    red[tid] = h;
    __syncthreads();
    for (int s = 128; s >= 1; s >>= 1) {
        if (tid < s) red[tid] += red[tid + s];
        __syncthreads();
    }
    if (tid == 0) {
        if (out_size > LOSS_OFF) out[LOSS_OFF] = loss;
        if (out_size > PERP_OFF) out[PERP_OFF] = expf(-red[0]);
    }
}

// ---------------------------------------------------------------------------
extern "C" void kernel_launch(void* const* d_in, const int* in_sizes, int n_in,
                              void* d_out, int out_size) {
    const float* z = (const float*)d_in[0];
    const float* w = (const float*)d_in[1];
    if (n_in >= 2 && in_sizes[0] == N_E * E_DIM && in_sizes[1] == OUT_ELEMS) {
        const float* tmp = z; z = w; w = tmp;
    }
    float* out = (float*)d_out;

    cudaFuncSetAttribute(argmin_kernel,
                         cudaFuncAttributeMaxDynamicSharedMemorySize, SMEM_BYTES);

    zero_kernel<<<32, 256>>>();
    transpose_kernel<<<dim3(8, 256), dim3(32, 8)>>>(w);
    wn_kernel<<<N_E / 256, 256>>>();
    argmin_kernel<<<dim3(N_TOK / BM, N_HALF), 256, SMEM_BYTES>>>(z);
    merge_kernel<<<N_TOK / 256, 256>>>();
    gather_kernel<<<N_TOK / 64, 256>>>(z, out, out_size);
    final_kernel<<<1, 256>>>(out, out_size);
}